// round 1
// baseline (speedup 1.0000x reference)
#include <cuda_runtime.h>

#define Bdim 512
#define Ldim 512
#define Tdim 128
#define START_TAG 126
#define STOP_TAG 127
#define NEGV (-10000.0f)
#define LOG2E 1.4426950408889634f

// per-batch (forward_score - gold_score)
__device__ float g_partial[Bdim];

__global__ __launch_bounds__(Tdim) void crf_batch_kernel(
    const float* __restrict__ feats,        // [B, L, T]
    const float* __restrict__ trans,        // [T, T]  trans[next, prev]
    const int*   __restrict__ tags,         // [B, L]
    const int*   __restrict__ lens)         // [B]
{
    const int b    = blockIdx.x;
    const int t    = threadIdx.x;           // this thread owns state 't'
    const int lane = t & 31;
    const int warp = t >> 5;

    __shared__ float gs[Tdim];              // exp(fv - m)
    __shared__ float smax[4];
    __shared__ float ssum[4];

    const int len = lens[b];

    // ---- precompute exp(trans[t, :]) into registers (row 'next' = t) ----
    float et[Tdim];
    {
        const float4* trow = reinterpret_cast<const float4*>(trans + t * Tdim);
        #pragma unroll
        for (int p4 = 0; p4 < Tdim / 4; p4++) {
            float4 v = trow[p4];
            et[4 * p4 + 0] = exp2f(v.x * LOG2E);
            et[4 * p4 + 1] = exp2f(v.y * LOG2E);
            et[4 * p4 + 2] = exp2f(v.z * LOG2E);
            et[4 * p4 + 3] = exp2f(v.w * LOG2E);
        }
    }

    // ---- forward recursion ----
    float fv = (t == START_TAG) ? 0.0f : NEGV;
    const float* emit_ptr = feats + (b * Ldim) * Tdim + t;

    for (int i = 0; i < len; i++) {
        // prefetch emission early; consumed at end of step
        float e = emit_ptr[i * Tdim];

        // block max of fv
        float m = fv;
        #pragma unroll
        for (int o = 16; o > 0; o >>= 1)
            m = fmaxf(m, __shfl_xor_sync(0xffffffffu, m, o));
        if (lane == 0) smax[warp] = m;
        __syncthreads();
        m = fmaxf(fmaxf(smax[0], smax[1]), fmaxf(smax[2], smax[3]));

        gs[t] = exp2f((fv - m) * LOG2E);
        __syncthreads();

        // s[t] = sum_p exp(trans[t,p]) * exp(fv[p]-m)
        float s0 = 0.f, s1 = 0.f, s2 = 0.f, s3 = 0.f;
        const float4* g4 = reinterpret_cast<const float4*>(gs);
        #pragma unroll
        for (int p4 = 0; p4 < Tdim / 4; p4++) {
            float4 gg = g4[p4];
            s0 += et[4 * p4 + 0] * gg.x;
            s1 += et[4 * p4 + 1] * gg.y;
            s2 += et[4 * p4 + 2] * gg.z;
            s3 += et[4 * p4 + 3] * gg.w;
        }
        float s = (s0 + s1) + (s2 + s3);

        fv = e + __logf(s) + m;
    }
    __syncthreads();

    // ---- forward score: LSE_t( fv[t] + trans[START, t] ) ----
    float term = fv + trans[START_TAG * Tdim + t];
    {
        float m2 = term;
        #pragma unroll
        for (int o = 16; o > 0; o >>= 1)
            m2 = fmaxf(m2, __shfl_xor_sync(0xffffffffu, m2, o));
        if (lane == 0) smax[warp] = m2;
        __syncthreads();
        m2 = fmaxf(fmaxf(smax[0], smax[1]), fmaxf(smax[2], smax[3]));

        float ex = exp2f((term - m2) * LOG2E);
        #pragma unroll
        for (int o = 16; o > 0; o >>= 1)
            ex += __shfl_xor_sync(0xffffffffu, ex, o);
        if (lane == 0) ssum[warp] = ex;
        __syncthreads();
        float tot = (ssum[0] + ssum[1]) + (ssum[2] + ssum[3]);
        term = m2 + __logf(tot);          // term now holds forward_score
        __syncthreads();                   // protect ssum reuse below
    }

    // ---- gold score ----
    float acc = 0.f;
    const int* tg = tags + b * Ldim;
    // transition terms, j = 0..len inclusive
    for (int j = t; j <= len; j += Tdim) {
        int pa, pb;
        if (j == 0)        { pa = START_TAG;  pb = tg[0];     }
        else if (j == len) { pa = tg[len - 1]; pb = STOP_TAG; }
        else               { pa = tg[j - 1];  pb = tg[j];     }
        acc += trans[pb * Tdim + pa];
    }
    // emission terms, i = 0..len-1
    for (int i = t; i < len; i += Tdim) {
        int tag = tg[i];
        acc += feats[(b * Ldim + i) * Tdim + tag];
    }
    {
        #pragma unroll
        for (int o = 16; o > 0; o >>= 1)
            acc += __shfl_xor_sync(0xffffffffu, acc, o);
        if (lane == 0) ssum[warp] = acc;
        __syncthreads();
        float gold = (ssum[0] + ssum[1]) + (ssum[2] + ssum[3]);
        if (t == 0) g_partial[b] = term - gold;
    }
}

__global__ __launch_bounds__(Bdim) void crf_reduce_kernel(float* __restrict__ out)
{
    __shared__ float sh[16];
    int t = threadIdx.x;
    float v = g_partial[t];
    #pragma unroll
    for (int o = 16; o > 0; o >>= 1)
        v += __shfl_xor_sync(0xffffffffu, v, o);
    if ((t & 31) == 0) sh[t >> 5] = v;
    __syncthreads();
    if (t < 32) {
        float w = (t < 16) ? sh[t] : 0.f;
        #pragma unroll
        for (int o = 8; o > 0; o >>= 1)
            w += __shfl_xor_sync(0xffffffffu, w, o);
        if (t == 0) out[0] = w * (1.0f / (float)Bdim);
    }
}

extern "C" void kernel_launch(void* const* d_in, const int* in_sizes, int n_in,
                              void* d_out, int out_size)
{
    const float* feats = (const float*)d_in[0];
    const float* trans = (const float*)d_in[1];
    const int*   tags  = (const int*)d_in[2];
    const int*   lens  = (const int*)d_in[3];
    float* out = (float*)d_out;

    crf_batch_kernel<<<Bdim, Tdim>>>(feats, trans, tags, lens);
    crf_reduce_kernel<<<1, Bdim>>>(out);
}

// round 2
// speedup vs baseline: 1.0164x; 1.0164x over previous
#include <cuda_runtime.h>
#include <string.h>

#define Bdim 512
#define Ldim 512
#define Tdim 128
#define START_TAG 126
#define STOP_TAG 127
#define NEGV (-10000.0f)
#define LOG2E 1.4426950408889634f
#define NCTA (Bdim / 2)

// per-batch (forward_score - gold_score)
__device__ float g_partial[Bdim];

__device__ __forceinline__ void fma2(unsigned long long& d,
                                     unsigned long long a,
                                     unsigned long long b) {
    asm("fma.rn.f32x2 %0, %1, %2, %0;" : "+l"(d) : "l"(a), "l"(b));
}

// s[t] = sum_p et[t,p] * gs[p], with et packed f32x2 in registers
__device__ __forceinline__ float matvec128(const float* gs,
                                           const unsigned long long* et) {
    const ulonglong2* g2 = reinterpret_cast<const ulonglong2*>(gs);
    unsigned long long a0 = 0, a1 = 0, a2 = 0, a3 = 0;
    #pragma unroll
    for (int k = 0; k < 32; k += 2) {
        ulonglong2 u = g2[k];
        ulonglong2 v = g2[k + 1];
        fma2(a0, et[2 * k + 0], u.x);
        fma2(a1, et[2 * k + 1], u.y);
        fma2(a2, et[2 * k + 2], v.x);
        fma2(a3, et[2 * k + 3], v.y);
    }
    float2 f0, f1, f2, f3;
    memcpy(&f0, &a0, 8); memcpy(&f1, &a1, 8);
    memcpy(&f2, &a2, 8); memcpy(&f3, &a3, 8);
    return ((f0.x + f0.y) + (f1.x + f1.y)) + ((f2.x + f2.y) + (f3.x + f3.y));
}

// terminal LSE + gold score for one batch; returns forward_score - gold_score
// (valid in all threads; uses smax/ssum with internal barriers)
__device__ __forceinline__ float finish_batch(
    float fv, int len, int b, int t, int lane, int warp,
    const float* __restrict__ feats, const float* __restrict__ trans,
    const int* __restrict__ tags, float* smax, float* ssum)
{
    // forward score: LSE_t( fv[t] + trans[START, t] )
    float term = fv + trans[START_TAG * Tdim + t];
    float m2 = term;
    #pragma unroll
    for (int o = 16; o > 0; o >>= 1)
        m2 = fmaxf(m2, __shfl_xor_sync(0xffffffffu, m2, o));
    if (lane == 0) smax[warp] = m2;
    __syncthreads();
    m2 = fmaxf(fmaxf(smax[0], smax[1]), fmaxf(smax[2], smax[3]));

    float ex = exp2f((term - m2) * LOG2E);
    #pragma unroll
    for (int o = 16; o > 0; o >>= 1)
        ex += __shfl_xor_sync(0xffffffffu, ex, o);
    if (lane == 0) ssum[warp] = ex;
    __syncthreads();
    float fwd = m2 + __logf((ssum[0] + ssum[1]) + (ssum[2] + ssum[3]));
    __syncthreads();

    // gold score
    float acc = 0.f;
    const int* tg = tags + b * Ldim;
    for (int j = t; j <= len; j += Tdim) {
        int pa, pb;
        if (j == 0)        { pa = START_TAG;   pb = tg[0];    }
        else if (j == len) { pa = tg[len - 1]; pb = STOP_TAG; }
        else               { pa = tg[j - 1];   pb = tg[j];    }
        acc += trans[pb * Tdim + pa];
    }
    for (int i = t; i < len; i += Tdim) {
        int tag = tg[i];
        acc += feats[(b * Ldim + i) * Tdim + tag];
    }
    #pragma unroll
    for (int o = 16; o > 0; o >>= 1)
        acc += __shfl_xor_sync(0xffffffffu, acc, o);
    if (lane == 0) ssum[warp] = acc;
    __syncthreads();
    float gold = (ssum[0] + ssum[1]) + (ssum[2] + ssum[3]);
    __syncthreads();
    return fwd - gold;
}

__global__ __launch_bounds__(Tdim) void crf_batch_kernel(
    const float* __restrict__ feats,        // [B, L, T]
    const float* __restrict__ trans,        // [T, T]  trans[next, prev]
    const int*   __restrict__ tags,         // [B, L]
    const int*   __restrict__ lens)         // [B]
{
    const int b1   = blockIdx.x;            // batches b1 and b2 per CTA
    const int b2   = blockIdx.x + NCTA;
    const int t    = threadIdx.x;           // this thread owns state 't'
    const int lane = t & 31;
    const int warp = t >> 5;

    __shared__ __align__(16) float gs1[Tdim];
    __shared__ __align__(16) float gs2[Tdim];
    __shared__ float sh_m[2];
    __shared__ float smax[4];
    __shared__ float ssum[4];

    const int len1 = lens[b1];
    const int len2 = lens[b2];
    const int lenmax = max(len1, len2);

    // ---- precompute exp(trans[t, :]) packed f32x2 into registers ----
    unsigned long long et[Tdim / 2];
    {
        const float4* trow = reinterpret_cast<const float4*>(trans + t * Tdim);
        #pragma unroll
        for (int k = 0; k < Tdim / 4; k++) {
            float4 v = trow[k];
            float2 lo = make_float2(exp2f(v.x * LOG2E), exp2f(v.y * LOG2E));
            float2 hi = make_float2(exp2f(v.z * LOG2E), exp2f(v.w * LOG2E));
            memcpy(&et[2 * k + 0], &lo, 8);
            memcpy(&et[2 * k + 1], &hi, 8);
        }
    }

    // ---- forward recursion for both batches ----
    float fv1 = (t == START_TAG) ? 0.0f : NEGV;
    float fv2 = fv1;
    const float* emit1 = feats + (size_t)b1 * Ldim * Tdim + t;
    const float* emit2 = feats + (size_t)b2 * Ldim * Tdim + t;

    if (t == 0) { sh_m[0] = 0.0f; sh_m[1] = 0.0f; }   // initial shift: max(fv0)=0

    for (int i = 0; i < lenmax; i++) {
        const bool act1 = (i < len1);
        const bool act2 = (i < len2);
        float e1 = act1 ? emit1[i * Tdim] : 0.0f;     // prefetch emissions early
        float e2 = act2 ? emit2[i * Tdim] : 0.0f;

        __syncthreads();                               // sh_m + prev-iter gs reads
        float m1 = sh_m[0];
        float m2 = sh_m[1];
        if (act1) gs1[t] = exp2f((fv1 - m1) * LOG2E);
        if (act2) gs2[t] = exp2f((fv2 - m2) * LOG2E);
        __syncthreads();                               // gs visible

        if (act1) {
            float s = matvec128(gs1, et);
            fv1 = e1 + __logf(s) + m1;
        }
        if (act2) {
            float s = matvec128(gs2, et);
            fv2 = e2 + __logf(s) + m2;
        }
        if (t == 0) { sh_m[0] = fv1; sh_m[1] = fv2; }  // next shift: thread0's fv
    }
    __syncthreads();

    float r1 = finish_batch(fv1, len1, b1, t, lane, warp, feats, trans, tags, smax, ssum);
    float r2 = finish_batch(fv2, len2, b2, t, lane, warp, feats, trans, tags, smax, ssum);
    if (t == 0) { g_partial[b1] = r1; g_partial[b2] = r2; }
}

__global__ __launch_bounds__(Bdim) void crf_reduce_kernel(float* __restrict__ out)
{
    __shared__ float sh[16];
    int t = threadIdx.x;
    float v = g_partial[t];
    #pragma unroll
    for (int o = 16; o > 0; o >>= 1)
        v += __shfl_xor_sync(0xffffffffu, v, o);
    if ((t & 31) == 0) sh[t >> 5] = v;
    __syncthreads();
    if (t < 32) {
        float w = (t < 16) ? sh[t] : 0.f;
        #pragma unroll
        for (int o = 8; o > 0; o >>= 1)
            w += __shfl_xor_sync(0xffffffffu, w, o);
        if (t == 0) out[0] = w * (1.0f / (float)Bdim);
    }
}

extern "C" void kernel_launch(void* const* d_in, const int* in_sizes, int n_in,
                              void* d_out, int out_size)
{
    const float* feats = (const float*)d_in[0];
    const float* trans = (const float*)d_in[1];
    const int*   tags  = (const int*)d_in[2];
    const int*   lens  = (const int*)d_in[3];
    float* out = (float*)d_out;

    crf_batch_kernel<<<NCTA, Tdim>>>(feats, trans, tags, lens);
    crf_reduce_kernel<<<1, Bdim>>>(out);
}

// round 3
// speedup vs baseline: 1.4562x; 1.4327x over previous
#include <cuda_runtime.h>
#include <string.h>

#define Bdim 512
#define Ldim 512
#define Tdim 128
#define START_TAG 126
#define STOP_TAG 127
#define NEGV (-10000.0f)
#define LOG2E 1.4426950408889634f
#define PF 8            // emission prefetch depth / unroll factor

// per-batch (forward_score - gold_score)
__device__ float g_partial[Bdim];

__device__ __forceinline__ void fma2(unsigned long long& d,
                                     unsigned long long a,
                                     unsigned long long b) {
    asm("fma.rn.f32x2 %0, %1, %2, %0;" : "+l"(d) : "l"(a), "l"(b));
}

// s[t] = sum_p et[t,p] * gs[p], et packed f32x2 in registers
__device__ __forceinline__ float matvec128(const float* gs,
                                           const unsigned long long* et) {
    const ulonglong2* g2 = reinterpret_cast<const ulonglong2*>(gs);
    unsigned long long a0 = 0, a1 = 0, a2 = 0, a3 = 0;
    #pragma unroll
    for (int k = 0; k < 32; k += 2) {
        ulonglong2 u = g2[k];
        ulonglong2 v = g2[k + 1];
        fma2(a0, et[2 * k + 0], u.x);
        fma2(a1, et[2 * k + 1], u.y);
        fma2(a2, et[2 * k + 2], v.x);
        fma2(a3, et[2 * k + 3], v.y);
    }
    float2 f0, f1, f2, f3;
    memcpy(&f0, &a0, 8); memcpy(&f1, &a1, 8);
    memcpy(&f2, &a2, 8); memcpy(&f3, &a3, 8);
    return ((f0.x + f0.y) + (f1.x + f1.y)) + ((f2.x + f2.y) + (f3.x + f3.y));
}

// terminal LSE + gold score; returns forward_score - gold_score (all threads)
__device__ __forceinline__ float finish_batch(
    float fv, int len, int b, int t, int lane, int warp,
    const float* __restrict__ feats, const float* __restrict__ trans,
    const int* __restrict__ tags, float* smax, float* ssum)
{
    float term = fv + trans[START_TAG * Tdim + t];
    float m2 = term;
    #pragma unroll
    for (int o = 16; o > 0; o >>= 1)
        m2 = fmaxf(m2, __shfl_xor_sync(0xffffffffu, m2, o));
    if (lane == 0) smax[warp] = m2;
    __syncthreads();
    m2 = fmaxf(fmaxf(smax[0], smax[1]), fmaxf(smax[2], smax[3]));

    float ex = exp2f((term - m2) * LOG2E);
    #pragma unroll
    for (int o = 16; o > 0; o >>= 1)
        ex += __shfl_xor_sync(0xffffffffu, ex, o);
    if (lane == 0) ssum[warp] = ex;
    __syncthreads();
    float fwd = m2 + __logf((ssum[0] + ssum[1]) + (ssum[2] + ssum[3]));
    __syncthreads();

    float acc = 0.f;
    const int* tg = tags + b * Ldim;
    for (int j = t; j <= len; j += Tdim) {
        int pa, pb;
        if (j == 0)        { pa = START_TAG;   pb = tg[0];    }
        else if (j == len) { pa = tg[len - 1]; pb = STOP_TAG; }
        else               { pa = tg[j - 1];   pb = tg[j];    }
        acc += trans[pb * Tdim + pa];
    }
    for (int i = t; i < len; i += Tdim) {
        int tag = tg[i];
        acc += feats[((size_t)b * Ldim + i) * Tdim + tag];
    }
    #pragma unroll
    for (int o = 16; o > 0; o >>= 1)
        acc += __shfl_xor_sync(0xffffffffu, acc, o);
    if (lane == 0) ssum[warp] = acc;
    __syncthreads();
    float gold = (ssum[0] + ssum[1]) + (ssum[2] + ssum[3]);
    __syncthreads();
    return fwd - gold;
}

__global__ __launch_bounds__(Tdim) void crf_batch_kernel(
    const float* __restrict__ feats,        // [B, L, T]
    const float* __restrict__ trans,        // [T, T]  trans[next, prev]
    const int*   __restrict__ tags,         // [B, L]
    const int*   __restrict__ lens)         // [B]
{
    const int b    = blockIdx.x;
    const int t    = threadIdx.x;           // this thread owns state 't'
    const int lane = t & 31;
    const int warp = t >> 5;

    __shared__ __align__(16) float gs[2][Tdim];  // double-buffered exp(fv - m)
    __shared__ float sh_m[2];                    // thread0's fv broadcast
    __shared__ float smax[4];
    __shared__ float ssum[4];

    const int len = lens[b];

    // ---- precompute exp(trans[t, :]) packed f32x2 into registers ----
    unsigned long long et[Tdim / 2];
    {
        const float4* trow = reinterpret_cast<const float4*>(trans + t * Tdim);
        #pragma unroll
        for (int k = 0; k < Tdim / 4; k++) {
            float4 v = trow[k];
            float2 lo = make_float2(exp2f(v.x * LOG2E), exp2f(v.y * LOG2E));
            float2 hi = make_float2(exp2f(v.z * LOG2E), exp2f(v.w * LOG2E));
            memcpy(&et[2 * k + 0], &lo, 8);
            memcpy(&et[2 * k + 1], &hi, 8);
        }
    }

    // ---- init: fv^(0), gs[0] = exp(fv^(0) - 0), shift m_0 = 0 ----
    float fv = (t == START_TAG) ? 0.0f : NEGV;
    float m_cur = 0.0f;
    gs[0][t] = (t == START_TAG) ? 1.0f : 0.0f;
    if (t == 0) sh_m[0] = 0.0f;

    const float* emit = feats + (size_t)b * Ldim * Tdim + t;
    const int lenm1 = len - 1;

    // ---- emission prefetch ring ----
    float e[PF];
    #pragma unroll
    for (int k = 0; k < PF; k++)
        e[k] = emit[min(k, lenm1) * Tdim];

    __syncthreads();

    // ---- forward recursion, padded to multiple of PF, one barrier/step ----
    const int len_pad = (len + PF - 1) & ~(PF - 1);
    for (int i0 = 0; i0 < len_pad; i0 += PF) {
        #pragma unroll
        for (int j = 0; j < PF; j++) {
            const int i = i0 + j;
            const int p = i & 1;
            const bool act = (i < len);            // block-uniform

            float ecur = e[j];
            e[j] = emit[min(i + PF, lenm1) * Tdim];  // prefetch step i+PF

            float s = matvec128(gs[p], et);
            float m_next = sh_m[p];                // thread0's fv, 1-gen stale
            if (act) {
                fv = ecur + __logf(s) + m_cur;
                gs[p ^ 1][t] = exp2f((fv - m_next) * LOG2E);
                if (t == 0) sh_m[p ^ 1] = fv;
            }
            m_cur = m_next;
            __syncthreads();
        }
    }

    float r = finish_batch(fv, len, b, t, lane, warp, feats, trans, tags, smax, ssum);
    if (t == 0) g_partial[b] = r;
}

__global__ __launch_bounds__(Bdim) void crf_reduce_kernel(float* __restrict__ out)
{
    __shared__ float sh[16];
    int t = threadIdx.x;
    float v = g_partial[t];
    #pragma unroll
    for (int o = 16; o > 0; o >>= 1)
        v += __shfl_xor_sync(0xffffffffu, v, o);
    if ((t & 31) == 0) sh[t >> 5] = v;
    __syncthreads();
    if (t < 32) {
        float w = (t < 16) ? sh[t] : 0.f;
        #pragma unroll
        for (int o = 8; o > 0; o >>= 1)
            w += __shfl_xor_sync(0xffffffffu, w, o);
        if (t == 0) out[0] = w * (1.0f / (float)Bdim);
    }
}

extern "C" void kernel_launch(void* const* d_in, const int* in_sizes, int n_in,
                              void* d_out, int out_size)
{
    const float* feats = (const float*)d_in[0];
    const float* trans = (const float*)d_in[1];
    const int*   tags  = (const int*)d_in[2];
    const int*   lens  = (const int*)d_in[3];
    float* out = (float*)d_out;

    crf_batch_kernel<<<Bdim, Tdim>>>(feats, trans, tags, lens);
    crf_reduce_kernel<<<1, Bdim>>>(out);
}

// round 4
// speedup vs baseline: 1.7017x; 1.1686x over previous
#include <cuda_runtime.h>
#include <string.h>

#define Bdim 512
#define Ldim 512
#define Tdim 128
#define START_TAG 126
#define STOP_TAG 127
#define NEGV (-10000.0f)
#define LOG2E 1.4426950408889634f
#define LN2   0.6931471805599453f
#define PF 8              // emission prefetch depth / unroll factor
#define NWORK 304         // persistent CTAs (~2 per SM on 152 SMs)

__device__ float g_partial[Bdim];     // per-batch forward - gold
__device__ int   g_counter;           // work queue head
__device__ int   g_order[Bdim];       // batch ids sorted by len desc

__device__ __forceinline__ void fma2(unsigned long long& d,
                                     unsigned long long a,
                                     unsigned long long b) {
    asm("fma.rn.f32x2 %0, %1, %2, %0;" : "+l"(d) : "l"(a), "l"(b));
}
__device__ __forceinline__ float rcp_fast(float x) {
    float r;
    asm("rcp.approx.f32 %0, %1;" : "=f"(r) : "f"(x));
    return r;
}

// s[t] = sum_p et[t,p] * gs[p], et packed f32x2 in registers
__device__ __forceinline__ float matvec128(const float* gs,
                                           const unsigned long long* et) {
    const ulonglong2* g2 = reinterpret_cast<const ulonglong2*>(gs);
    unsigned long long a0 = 0, a1 = 0, a2 = 0, a3 = 0;
    #pragma unroll
    for (int k = 0; k < 32; k += 2) {
        ulonglong2 u = g2[k];
        ulonglong2 v = g2[k + 1];
        fma2(a0, et[2 * k + 0], u.x);
        fma2(a1, et[2 * k + 1], u.y);
        fma2(a2, et[2 * k + 2], v.x);
        fma2(a3, et[2 * k + 3], v.y);
    }
    float2 f0, f1, f2, f3;
    memcpy(&f0, &a0, 8); memcpy(&f1, &a1, 8);
    memcpy(&f2, &a2, 8); memcpy(&f3, &a3, 8);
    return ((f0.x + f0.y) + (f1.x + f1.y)) + ((f2.x + f2.y) + (f3.x + f3.y));
}

// terminal LSE + gold score; returns forward_score - gold_score (all threads)
__device__ __forceinline__ float finish_batch(
    float fv, int len, int b, int t, int lane, int warp,
    const float* __restrict__ feats, const float* __restrict__ trans,
    const int* __restrict__ tags, float* smax, float* ssum)
{
    float term = fv + trans[START_TAG * Tdim + t];
    float m2 = term;
    #pragma unroll
    for (int o = 16; o > 0; o >>= 1)
        m2 = fmaxf(m2, __shfl_xor_sync(0xffffffffu, m2, o));
    if (lane == 0) smax[warp] = m2;
    __syncthreads();
    m2 = fmaxf(fmaxf(smax[0], smax[1]), fmaxf(smax[2], smax[3]));

    float ex = exp2f((term - m2) * LOG2E);
    #pragma unroll
    for (int o = 16; o > 0; o >>= 1)
        ex += __shfl_xor_sync(0xffffffffu, ex, o);
    if (lane == 0) ssum[warp] = ex;
    __syncthreads();
    float fwd = m2 + __logf((ssum[0] + ssum[1]) + (ssum[2] + ssum[3]));
    __syncthreads();

    float acc = 0.f;
    const int* tg = tags + b * Ldim;
    for (int j = t; j <= len; j += Tdim) {
        int pa, pb;
        if (j == 0)        { pa = START_TAG;   pb = tg[0];    }
        else if (j == len) { pa = tg[len - 1]; pb = STOP_TAG; }
        else               { pa = tg[j - 1];   pb = tg[j];    }
        acc += trans[pb * Tdim + pa];
    }
    for (int i = t; i < len; i += Tdim) {
        int tag = tg[i];
        acc += feats[((size_t)b * Ldim + i) * Tdim + tag];
    }
    #pragma unroll
    for (int o = 16; o > 0; o >>= 1)
        acc += __shfl_xor_sync(0xffffffffu, acc, o);
    if (lane == 0) ssum[warp] = acc;
    __syncthreads();
    float gold = (ssum[0] + ssum[1]) + (ssum[2] + ssum[3]);
    __syncthreads();
    return fwd - gold;
}

// kernel A: rank batches by length (desc, stable) + reset work counter
__global__ __launch_bounds__(Bdim) void crf_schedule_kernel(const int* __restrict__ lens)
{
    __shared__ int sl[Bdim];
    int t = threadIdx.x;
    sl[t] = lens[t];
    __syncthreads();
    int myl = sl[t];
    int rank = 0;
    #pragma unroll 8
    for (int j = 0; j < Bdim; j++) {
        int lj = sl[j];
        rank += (lj > myl) || (lj == myl && j < t);
    }
    g_order[rank] = t;
    if (t == 0) g_counter = NWORK;
}

__global__ __launch_bounds__(Tdim) void crf_batch_kernel(
    const float* __restrict__ feats,        // [B, L, T]
    const float* __restrict__ trans,        // [T, T]  trans[next, prev]
    const int*   __restrict__ tags,         // [B, L]
    const int*   __restrict__ lens)         // [B]
{
    const int t    = threadIdx.x;           // this thread owns state 't'
    const int lane = t & 31;
    const int warp = t >> 5;

    __shared__ __align__(16) float gs[2][Tdim];  // double-buffered G (linear domain)
    __shared__ float sh_w[2];                    // thread0's unnormalized update
    __shared__ float smax[4];
    __shared__ float ssum[4];
    __shared__ int   sh_job;

    // ---- precompute exp(trans[t, :]) packed f32x2 into registers ----
    unsigned long long et[Tdim / 2];
    {
        const float4* trow = reinterpret_cast<const float4*>(trans + t * Tdim);
        #pragma unroll
        for (int k = 0; k < Tdim / 4; k++) {
            float4 v = trow[k];
            float2 lo = make_float2(exp2f(v.x * LOG2E), exp2f(v.y * LOG2E));
            float2 hi = make_float2(exp2f(v.z * LOG2E), exp2f(v.w * LOG2E));
            memcpy(&et[2 * k + 0], &lo, 8);
            memcpy(&et[2 * k + 1], &hi, 8);
        }
    }

    int job = blockIdx.x;
    while (job < Bdim) {
        const int b   = g_order[job];
        const int len = lens[b];
        const int lenm1 = len - 1;

        // init: G_0 = exp(fv0 - 0) = indicator(START); shift M2 = 0; w0 = 1
        gs[0][t] = (t == START_TAG) ? 1.0f : 0.0f;
        if (t == 0) sh_w[0] = 1.0f;
        float Gcur = (t == START_TAG) ? 1.0f : 0.0f;
        float Macc = 0.0f;                       // accumulated shift, log2 domain

        const float* emit = feats + (size_t)b * Ldim * Tdim + t;

        // prefetch ring holds exp(emit)
        float ee[PF];
        #pragma unroll
        for (int k = 0; k < PF; k++)
            ee[k] = exp2f(emit[min(k, lenm1) * Tdim] * LOG2E);

        __syncthreads();

        const int len_pad = (len + PF - 1) & ~(PF - 1);
        for (int i0 = 0; i0 < len_pad; i0 += PF) {
            #pragma unroll
            for (int j = 0; j < PF; j++) {
                const int i = i0 + j;
                const int p = i & 1;
                const bool act = (i < len);          // block-uniform

                float eecur = ee[j];
                // prefetch exp(emit) for step i+PF (off-chain)
                float enew = emit[min(i + PF, lenm1) * Tdim];
                ee[j] = exp2f(enew * LOG2E);

                float w = sh_w[p];                   // stale normalizer (>0)
                float r = rcp_fast(w);               // off-chain MUFU

                float s = matvec128(gs[p], et);      // the critical chain
                float u = s * eecur;                 // unnormalized update
                if (act) {
                    float G2 = u * r;
                    gs[p ^ 1][t] = G2;
                    if (t == 0) sh_w[p ^ 1] = u;
                    Gcur = G2;
                    Macc += __log2f(w);              // shadow accumulation
                }
                __syncthreads();
            }
        }

        // fv[t] = ln2 * (log2(G) + Macc); G==0 (START row) -> -inf, handled in LSE
        float fv = (__log2f(Gcur) + Macc) * LN2;

        float res = finish_batch(fv, len, b, t, lane, warp,
                                 feats, trans, tags, smax, ssum);
        if (t == 0) {
            g_partial[b] = res;
            sh_job = atomicAdd(&g_counter, 1);
        }
        __syncthreads();
        job = sh_job;
        __syncthreads();
    }
}

__global__ __launch_bounds__(Bdim) void crf_reduce_kernel(float* __restrict__ out)
{
    __shared__ float sh[16];
    int t = threadIdx.x;
    float v = g_partial[t];
    #pragma unroll
    for (int o = 16; o > 0; o >>= 1)
        v += __shfl_xor_sync(0xffffffffu, v, o);
    if ((t & 31) == 0) sh[t >> 5] = v;
    __syncthreads();
    if (t < 32) {
        float w = (t < 16) ? sh[t] : 0.f;
        #pragma unroll
        for (int o = 8; o > 0; o >>= 1)
            w += __shfl_xor_sync(0xffffffffu, w, o);
        if (t == 0) out[0] = w * (1.0f / (float)Bdim);
    }
}

extern "C" void kernel_launch(void* const* d_in, const int* in_sizes, int n_in,
                              void* d_out, int out_size)
{
    const float* feats = (const float*)d_in[0];
    const float* trans = (const float*)d_in[1];
    const int*   tags  = (const int*)d_in[2];
    const int*   lens  = (const int*)d_in[3];
    float* out = (float*)d_out;

    crf_schedule_kernel<<<1, Bdim>>>(lens);
    crf_batch_kernel<<<NWORK, Tdim>>>(feats, trans, tags, lens);
    crf_reduce_kernel<<<1, Bdim>>>(out);
}